// round 9
// baseline (speedup 1.0000x reference)
#include <cuda_runtime.h>
#include <cuda_bf16.h>
#include <cstdint>

// N = 1048576 rows, D = 64 f32 per row (256 B/row).
constexpr int N_ELEMS = 1 << 20;
constexpr int TILE    = 256;                 // rows per block
constexpr int NTILES  = N_ELEMS / TILE;      // 4096
constexpr int PRED    = NTILES / 256;        // 16 predecessor slots per thread

// Per-tile published count, 32-bit packed: [21:32) ready-tag, [0:20) value.
// ready-tag = (epoch<<1)|1, epoch = launch number (10 bits). Every word is
// rewritten every launch, so stale words always mismatch -> no reset needed.
__device__ unsigned long long g_ticket;      // zero-init at module load
__device__ unsigned int      g_state[NTILES];

__global__ void __launch_bounds__(256, 5) stitch_k(
        const int*    __restrict__ part,
        const int*    __restrict__ idx0,
        const int*    __restrict__ idx1,
        const float4* __restrict__ in,
        float4*       __restrict__ out) {
    __shared__ unsigned long long s_ticket;
    __shared__ int wsum[8];     // per-warp zero counts
    __shared__ int rsum[8];     // per-warp predecessor partial sums
    __shared__ int sdest[TILE];

    int t = threadIdx.x;
    if (t == 0) s_ticket = atomicAdd(&g_ticket, 1ULL);
    __syncthreads();
    unsigned long long ticket = s_ticket;
    int tile = (int)(ticket & (unsigned long long)(NTILES - 1));
    unsigned int ready_tag = ((((unsigned int)(ticket >> 12)) & 0x3FFu) << 1) | 1u;
    unsigned int etag      = ready_tag << 21;

    int gi = tile * TILE + t;
    const float4* src = in + (size_t)tile * (TILE * 16);

    // --- publish this tile's aggregate ASAP (independent of all other blocks) ---
    int b = (part[gi] == 0);
    int lane = t & 31, w = t >> 5;
    unsigned bal = __ballot_sync(0xffffffffu, b);
    int within = __popc(bal & ((1u << lane) - 1u));
    if (lane == 0) wsum[w] = __popc(bal);
    __syncthreads();
    if (t == 0) {
        int cnt = 0;
        #pragma unroll
        for (int i = 0; i < 8; i++) cnt += wsum[i];
        atomicExch(&g_state[tile], etag | (unsigned int)cnt);
    }

    // --- prefetch first half of the tile's row data (32 regs, long latency) ---
    float4 v[8];
    #pragma unroll
    for (int k = 0; k < 8; k++) v[k] = src[t + k * 256];

    // --- predecessor sum: immediate-accumulate (short live ranges), respin
    //     only unready slots (wave-1 stragglers) ---
    int acc = 0;
    unsigned pending = 0;
    #pragma unroll
    for (int k = 0; k < PRED; k++) {
        int i = t + k * 256;
        unsigned int s = (i < tile) ? *(volatile unsigned int*)&g_state[i] : etag;
        bool ok = (s >> 21) == ready_tag;
        acc += ok ? (int)(s & 0xFFFFFu) : 0;
        pending |= ok ? 0u : (1u << k);
    }
    while (pending) {
        int k = __ffs(pending) - 1;
        unsigned int s = *(volatile unsigned int*)&g_state[t + k * 256];
        if ((s >> 21) == ready_tag) {
            acc += (int)(s & 0xFFFFFu);
            pending &= pending - 1;
        }
    }
    #pragma unroll
    for (int o = 16; o; o >>= 1) acc += __shfl_down_sync(0xffffffffu, acc, o);
    if (lane == 0) rsum[w] = acc;
    __syncthreads();

    // --- per-element destination ---
    int tileOff = 0, woff = 0;
    #pragma unroll
    for (int i = 0; i < 8; i++) {
        tileOff += rsum[i];
        woff    += (i < w) ? wsum[i] : 0;
    }
    int zb = tileOff + woff + within;            // global zeros strictly before gi
    sdest[t] = b ? __ldg(idx0 + zb) : __ldg(idx1 + (gi - zb));
    __syncthreads();

    // --- store prefetched half ---
    #pragma unroll
    for (int k = 0; k < 8; k++) {
        int s   = t + k * 256;
        int row = s >> 4;
        int ln  = s & 15;
        out[(size_t)sdest[row] * 16 + ln] = v[k];
    }
    // --- stream second half ---
    #pragma unroll
    for (int k = 8; k < 16; k++) {
        int s   = t + k * 256;
        int row = s >> 4;
        int ln  = s & 15;
        out[(size_t)sdest[row] * 16 + ln] = src[s];
    }
}

// ---------------------------------------------------------------------------
extern "C" void kernel_launch(void* const* d_in, const int* in_sizes, int n_in,
                              void* d_out, int out_size) {
    const float* data = (const float*)d_in[0];
    const int*   part = (const int*)d_in[1];
    const int*   idx0 = (const int*)d_in[2];
    const int*   idx1 = (const int*)d_in[3];
    float* out = (float*)d_out;

    stitch_k<<<NTILES, 256>>>(part, idx0, idx1,
                              (const float4*)data, (float4*)out);
}

// round 10
// speedup vs baseline: 1.1163x; 1.1163x over previous
#include <cuda_runtime.h>
#include <cuda_bf16.h>
#include <cstdint>

// N = 1048576 rows, D = 64 f32 per row (256 B/row).
constexpr int N_ELEMS = 1 << 20;
constexpr int TILE    = 256;                 // rows per block
constexpr int NTILES  = N_ELEMS / TILE;      // 4096
constexpr int PRED    = NTILES / 256;        // 16 predecessor slots per thread

// Per-tile published count, 32-bit packed: [21:32) ready-tag, [0:20) value.
// ready-tag = (epoch<<1)|1, epoch = launch number (10 bits). Every word is
// rewritten every launch, so stale words always mismatch -> no reset needed.
__device__ unsigned long long g_ticket;      // zero-init at module load
__device__ unsigned int      g_state[NTILES];

__global__ void __launch_bounds__(256) stitch_k(
        const int*    __restrict__ part,
        const int*    __restrict__ idx0,
        const int*    __restrict__ idx1,
        const float4* __restrict__ in,
        float4*       __restrict__ out) {
    __shared__ unsigned long long s_ticket;
    __shared__ int wsum[8];     // per-warp zero counts
    __shared__ int rsum[8];     // per-warp predecessor partial sums
    __shared__ int sdest[TILE];

    int t = threadIdx.x;
    if (t == 0) s_ticket = atomicAdd(&g_ticket, 1ULL);
    __syncthreads();
    unsigned long long ticket = s_ticket;
    int tile = (int)(ticket & (unsigned long long)(NTILES - 1));
    unsigned int ready_tag = ((((unsigned int)(ticket >> 12)) & 0x3FFu) << 1) | 1u;
    unsigned int etag      = ready_tag << 21;

    int gi = tile * TILE + t;
    const float4* src = in + (size_t)tile * (TILE * 16);

    // --- publish this tile's aggregate ASAP (independent of all other blocks) ---
    int b = (part[gi] == 0);
    int lane = t & 31, w = t >> 5;
    unsigned bal = __ballot_sync(0xffffffffu, b);
    int within = __popc(bal & ((1u << lane) - 1u));
    if (lane == 0) wsum[w] = __popc(bal);
    __syncthreads();
    if (t == 0) {
        int cnt = 0;
        #pragma unroll
        for (int i = 0; i < 8; i++) cnt += wsum[i];
        atomicExch(&g_state[tile], etag | (unsigned int)cnt);
    }

    // --- prefetch first half of the tile's row data (32 regs, long latency) ---
    float4 v[8];
    #pragma unroll
    for (int k = 0; k < 8; k++) v[k] = src[t + k * 256];

    // --- predecessor sum: fast pass on the L1/read-only path (parallel, cheap;
    //     a ready word never changes within a launch, so stale==unready only),
    //     then volatile respin on the rare wave-1 stragglers ---
    int acc = 0;
    unsigned pending = 0;
    #pragma unroll
    for (int k = 0; k < PRED; k++) {
        int i = t + k * 256;
        unsigned int s = (i < tile) ? __ldg((const unsigned int*)&g_state[i]) : etag;
        bool ok = (s >> 21) == ready_tag;
        acc += ok ? (int)(s & 0xFFFFFu) : 0;
        pending |= ok ? 0u : (1u << k);
    }
    while (pending) {
        int k = __ffs(pending) - 1;
        unsigned int s = *(volatile unsigned int*)&g_state[t + k * 256];
        if ((s >> 21) == ready_tag) {
            acc += (int)(s & 0xFFFFFu);
            pending &= pending - 1;
        }
    }
    #pragma unroll
    for (int o = 16; o; o >>= 1) acc += __shfl_down_sync(0xffffffffu, acc, o);
    if (lane == 0) rsum[w] = acc;
    __syncthreads();

    // --- per-element destination ---
    int tileOff = 0, woff = 0;
    #pragma unroll
    for (int i = 0; i < 8; i++) {
        tileOff += rsum[i];
        woff    += (i < w) ? wsum[i] : 0;
    }
    int zb = tileOff + woff + within;            // global zeros strictly before gi
    sdest[t] = b ? __ldg(idx0 + zb) : __ldg(idx1 + (gi - zb));
    __syncthreads();

    // --- store prefetched half ---
    #pragma unroll
    for (int k = 0; k < 8; k++) {
        int s   = t + k * 256;
        int row = s >> 4;
        int ln  = s & 15;
        out[(size_t)sdest[row] * 16 + ln] = v[k];
    }
    // --- stream second half ---
    #pragma unroll
    for (int k = 8; k < 16; k++) {
        int s   = t + k * 256;
        int row = s >> 4;
        int ln  = s & 15;
        out[(size_t)sdest[row] * 16 + ln] = src[s];
    }
}

// ---------------------------------------------------------------------------
extern "C" void kernel_launch(void* const* d_in, const int* in_sizes, int n_in,
                              void* d_out, int out_size) {
    const float* data = (const float*)d_in[0];
    const int*   part = (const int*)d_in[1];
    const int*   idx0 = (const int*)d_in[2];
    const int*   idx1 = (const int*)d_in[3];
    float* out = (float*)d_out;

    stitch_k<<<NTILES, 256>>>(part, idx0, idx1,
                              (const float4*)data, (float4*)out);
}